// round 2
// baseline (speedup 1.0000x reference)
#include <cuda_runtime.h>
#include <math.h>

#define FRAMES 32
#define FRAME_ELEMS (720*1280)          // 921600
#define TOTAL_ELEMS (FRAMES*FRAME_ELEMS)
#define NB 8192                         // histogram bins (tie err ~1e-8 in AUC)
#define BPF 225                         // blocks per frame: 225*256*16 = 921600
#define TPB 256

struct Stats {
    double sum_p[FRAMES];
    double sum_p2[FRAMES];
    double sum_fp[FRAMES];
    double cnt_fix[FRAMES];
    double sum_sim[FRAMES];
    double sum_g;
    unsigned pmin_enc, gmin_enc;        // global mins (SIM)
    unsigned p0min_enc, p0max_enc;      // frame-0 pred min/max (AUC binning)
};

__device__ Stats g_s;
__device__ unsigned g_hf[NB];
__device__ unsigned g_hn[NB];

// ---------- helpers ----------
__device__ __forceinline__ unsigned encF(float x) {
    unsigned u = __float_as_uint(x);
    return (u & 0x80000000u) ? ~u : (u | 0x80000000u);
}
__device__ __forceinline__ float decF(unsigned u) {
    u = (u & 0x80000000u) ? (u & 0x7FFFFFFFu) : ~u;
    return __uint_as_float(u);
}

// 256-thread block reductions
__device__ __forceinline__ double blkSumD(double v, double* sh) {
    #pragma unroll
    for (int o = 16; o; o >>= 1) v += __shfl_down_sync(0xFFFFFFFFu, v, o);
    if ((threadIdx.x & 31) == 0) sh[threadIdx.x >> 5] = v;
    __syncthreads();
    double r = 0.0;
    if (threadIdx.x < 32) {
        r = (threadIdx.x < 8) ? sh[threadIdx.x] : 0.0;
        #pragma unroll
        for (int o = 4; o; o >>= 1) r += __shfl_down_sync(0xFFFFFFFFu, r, o);
    }
    __syncthreads();
    return r;   // valid on thread 0
}

__device__ __forceinline__ float blkMinF(float v, float* sh) {
    #pragma unroll
    for (int o = 16; o; o >>= 1) v = fminf(v, __shfl_down_sync(0xFFFFFFFFu, v, o));
    if ((threadIdx.x & 31) == 0) sh[threadIdx.x >> 5] = v;
    __syncthreads();
    float r = 3.4e38f;
    if (threadIdx.x < 32) {
        r = (threadIdx.x < 8) ? sh[threadIdx.x] : 3.4e38f;
        #pragma unroll
        for (int o = 4; o; o >>= 1) r = fminf(r, __shfl_down_sync(0xFFFFFFFFu, r, o));
    }
    __syncthreads();
    return r;
}

__device__ __forceinline__ float blkMaxF(float v, float* sh) {
    #pragma unroll
    for (int o = 16; o; o >>= 1) v = fmaxf(v, __shfl_down_sync(0xFFFFFFFFu, v, o));
    if ((threadIdx.x & 31) == 0) sh[threadIdx.x >> 5] = v;
    __syncthreads();
    float r = -3.4e38f;
    if (threadIdx.x < 32) {
        r = (threadIdx.x < 8) ? sh[threadIdx.x] : -3.4e38f;
        #pragma unroll
        for (int o = 4; o; o >>= 1) r = fmaxf(r, __shfl_down_sync(0xFFFFFFFFu, r, o));
    }
    __syncthreads();
    return r;
}

// 1024-thread ull reduction
__device__ __forceinline__ unsigned long long blkSumU1024(unsigned long long v,
                                                          unsigned long long* sh) {
    #pragma unroll
    for (int o = 16; o; o >>= 1) v += __shfl_down_sync(0xFFFFFFFFu, v, o);
    if ((threadIdx.x & 31) == 0) sh[threadIdx.x >> 5] = v;
    __syncthreads();
    unsigned long long r = 0;
    if (threadIdx.x < 32) {
        r = sh[threadIdx.x];
        #pragma unroll
        for (int o = 16; o; o >>= 1) r += __shfl_down_sync(0xFFFFFFFFu, r, o);
    }
    __syncthreads();
    return r;
}

// ---------- kernels ----------
__global__ void k_init() {
    int t = threadIdx.x;
    if (t < FRAMES) {
        g_s.sum_p[t] = 0.0; g_s.sum_p2[t] = 0.0; g_s.sum_fp[t] = 0.0;
        g_s.cnt_fix[t] = 0.0; g_s.sum_sim[t] = 0.0;
    }
    if (t == 0) {
        g_s.sum_g = 0.0;
        g_s.pmin_enc = 0xFFFFFFFFu; g_s.gmin_enc = 0xFFFFFFFFu;
        g_s.p0min_enc = 0xFFFFFFFFu; g_s.p0max_enc = 0u;
    }
    for (int b = t; b < NB; b += 256) { g_hf[b] = 0u; g_hn[b] = 0u; }
}

// frame-0 pred min/max (for AUC bin scale, monotone binning)
__global__ void k_pre(const float* __restrict__ pred) {
    __shared__ float shf[8];
    size_t base = (size_t)blockIdx.x * 4096u;
    const float4* p4 = reinterpret_cast<const float4*>(pred + base);
    float mn = 3.4e38f, mx = -3.4e38f;
    #pragma unroll
    for (int k = 0; k < 4; k++) {
        float4 p = p4[threadIdx.x + 256 * k];
        mn = fminf(mn, fminf(fminf(p.x, p.y), fminf(p.z, p.w)));
        mx = fmaxf(mx, fmaxf(fmaxf(p.x, p.y), fmaxf(p.z, p.w)));
    }
    float rmn = blkMinF(mn, shf);
    float rmx = blkMaxF(mx, shf);
    if (threadIdx.x == 0) {
        atomicMin(&g_s.p0min_enc, encF(rmn));
        atomicMax(&g_s.p0max_enc, encF(rmx));
    }
}

// Pass 1: per-frame NSS stats + global mins + frame-0 AUC histogram
__global__ void k_main(const float* __restrict__ pred, const float* __restrict__ gt,
                       const int* __restrict__ fix) {
    __shared__ double shd[8];
    __shared__ float shf[8];
    int f = blockIdx.y;
    size_t base = (size_t)f * FRAME_ELEMS + (size_t)blockIdx.x * 4096u;
    const float4* p4 = reinterpret_cast<const float4*>(pred + base);
    const float4* g4 = reinterpret_cast<const float4*>(gt + base);
    const int4*   x4 = reinterpret_cast<const int4*>(fix + base);

    // frame-0 histogram constants (k_pre completed before this launch)
    float p0min = 0.f, scale = 0.f;
    bool doHist = (f == 0);
    if (doHist) {
        p0min = decF(g_s.p0min_enc);
        float p0max = decF(g_s.p0max_enc);
        scale = (float)NB / (p0max - p0min);
    }

    float sp = 0.f, sp2 = 0.f, sfp = 0.f, sg = 0.f, cf = 0.f;
    float pmn = 3.4e38f, gmn = 3.4e38f;
    #pragma unroll
    for (int k = 0; k < 4; k++) {
        int i = threadIdx.x + 256 * k;
        float4 p = p4[i]; float4 g = g4[i]; int4 x = x4[i];
        sp  += (p.x + p.y) + (p.z + p.w);
        sp2 += (p.x*p.x + p.y*p.y) + (p.z*p.z + p.w*p.w);
        sg  += (g.x + g.y) + (g.z + g.w);
        pmn = fminf(pmn, fminf(fminf(p.x, p.y), fminf(p.z, p.w)));
        gmn = fminf(gmn, fminf(fminf(g.x, g.y), fminf(g.z, g.w)));
        if (x.x) { sfp += p.x; cf += 1.f; }
        if (x.y) { sfp += p.y; cf += 1.f; }
        if (x.z) { sfp += p.z; cf += 1.f; }
        if (x.w) { sfp += p.w; cf += 1.f; }
        if (doHist) {
            int b0 = min(NB - 1, (int)((p.x - p0min) * scale));
            int b1 = min(NB - 1, (int)((p.y - p0min) * scale));
            int b2 = min(NB - 1, (int)((p.z - p0min) * scale));
            int b3 = min(NB - 1, (int)((p.w - p0min) * scale));
            atomicAdd(x.x ? &g_hf[b0] : &g_hn[b0], 1u);
            atomicAdd(x.y ? &g_hf[b1] : &g_hn[b1], 1u);
            atomicAdd(x.z ? &g_hf[b2] : &g_hn[b2], 1u);
            atomicAdd(x.w ? &g_hf[b3] : &g_hn[b3], 1u);
        }
    }
    double rs  = blkSumD((double)sp,  shd);
    double rs2 = blkSumD((double)sp2, shd);
    double rfp = blkSumD((double)sfp, shd);
    double rg  = blkSumD((double)sg,  shd);
    double rcf = blkSumD((double)cf,  shd);
    float rpmn = blkMinF(pmn, shf);
    float rgmn = blkMinF(gmn, shf);
    if (threadIdx.x == 0) {
        atomicAdd(&g_s.sum_p[f],  rs);
        atomicAdd(&g_s.sum_p2[f], rs2);
        atomicAdd(&g_s.sum_fp[f], rfp);
        atomicAdd(&g_s.cnt_fix[f], rcf);
        atomicAdd(&g_s.sum_g,     rg);
        atomicMin(&g_s.pmin_enc, encF(rpmn));
        atomicMin(&g_s.gmin_enc, encF(rgmn));
    }
}

// Pass 2: SIM (normalization constants derived per-block from pass-1 stats)
__global__ void k_sim(const float* __restrict__ pred, const float* __restrict__ gt) {
    __shared__ double shd[8];
    __shared__ float cN[4];   // pmin, gmin, invTp, invTg
    if (threadIdx.x == 0) {
        float pmin = decF(g_s.pmin_enc);
        float gmin = decF(g_s.gmin_enc);
        double sumP = 0.0;
        #pragma unroll
        for (int f = 0; f < FRAMES; f++) sumP += g_s.sum_p[f];
        double Tp = sumP - (double)TOTAL_ELEMS * (double)pmin;
        double Tg = g_s.sum_g - (double)TOTAL_ELEMS * (double)gmin;
        cN[0] = pmin; cN[1] = gmin;
        cN[2] = (float)(1.0 / Tp); cN[3] = (float)(1.0 / Tg);
    }
    __syncthreads();
    float pmin = cN[0], gmin = cN[1], ip = cN[2], ig = cN[3];

    int f = blockIdx.y;
    size_t base = (size_t)f * FRAME_ELEMS + (size_t)blockIdx.x * 4096u;
    const float4* p4 = reinterpret_cast<const float4*>(pred + base);
    const float4* g4 = reinterpret_cast<const float4*>(gt + base);
    float acc = 0.f;
    #pragma unroll
    for (int k = 0; k < 4; k++) {
        int i = threadIdx.x + 256 * k;
        float4 p = p4[i]; float4 g = g4[i];
        if (g.x > gmin) acc += fminf((g.x - gmin) * ig, (p.x - pmin) * ip);
        if (g.y > gmin) acc += fminf((g.y - gmin) * ig, (p.y - pmin) * ip);
        if (g.z > gmin) acc += fminf((g.z - gmin) * ig, (p.z - pmin) * ip);
        if (g.w > gmin) acc += fminf((g.w - gmin) * ig, (p.w - pmin) * ip);
    }
    double r = blkSumD((double)acc, shd);
    if (threadIdx.x == 0) atomicAdd(&g_s.sum_sim[f], r);
}

// One block: AUC from 8192-bin histogram (prefix-sum -> Mann-Whitney U) + final output
__global__ void k_auc(float* __restrict__ out) {
    __shared__ unsigned sc[1024];
    __shared__ unsigned long long shu[32];
    __shared__ int sB;
    int t = threadIdx.x;
    int base = t * 8;
    uint4 a0 = *reinterpret_cast<const uint4*>(&g_hf[base]);
    uint4 a1 = *reinterpret_cast<const uint4*>(&g_hf[base + 4]);
    uint4 b0 = *reinterpret_cast<const uint4*>(&g_hn[base]);
    uint4 b1 = *reinterpret_cast<const uint4*>(&g_hn[base + 4]);
    unsigned hf[8] = {a0.x, a0.y, a0.z, a0.w, a1.x, a1.y, a1.z, a1.w};
    unsigned hn[8] = {b0.x, b0.y, b0.z, b0.w, b1.x, b1.y, b1.z, b1.w};

    unsigned local = 0;
    #pragma unroll
    for (int i = 0; i < 8; i++) local += hf[i];
    if (t == 0) sB = NB;
    sc[t] = local;
    __syncthreads();
    // Hillis–Steele inclusive scan over 1024 partial fix-counts
    for (int o = 1; o < 1024; o <<= 1) {
        unsigned v = (t >= o) ? sc[t - o] : 0u;
        __syncthreads();
        sc[t] += v;
        __syncthreads();
    }
    unsigned F = sc[t] - local;   // exclusive prefix of fix counts

    // bstar = lowest bin containing a fixation
    int mn = NB;
    #pragma unroll
    for (int i = 0; i < 8; i++) if (hf[i] && base + i < mn) mn = base + i;
    atomicMin(&sB, mn);
    __syncthreads();
    int bstar = sB;

    unsigned long long u1 = 0, u2 = 0, u3 = 0;
    #pragma unroll
    for (int i = 0; i < 8; i++) {
        u1 += (unsigned long long)hn[i] * F;       // non-fix vs fix ranked above
        u2 += (unsigned long long)hf[i] * hn[i];   // within-bin ties (expected /2)
        if (base + i > bstar) u3 += hn[i];         // non-fix above last fixation
        F += hf[i];
    }
    u1 = blkSumU1024(u1, shu);
    u2 = blkSumU1024(u2, shu);
    u3 = blkSumU1024(u3, shu);

    if (t == 0) {
        double Np = (double)FRAME_ELEMS;
        double Nf = g_s.cnt_fix[0];
        double D  = Np - Nf;
        double S  = (double)u1 + 0.5 * (double)u2;
        double b  = (double)u3;
        double auc = ((2.0 * Nf + 1.0) * b + 1.0 - 2.0 * S) / (2.0 * Nf * D)
                   + 1.0 - (b + 1.0) / D;
        double sim = 0.0, nss = 0.0;
        for (int f = 0; f < FRAMES; f++) {
            sim += g_s.sum_sim[f];
            double m   = g_s.sum_p[f] / Np;
            double var = g_s.sum_p2[f] / Np - m * m;
            double sd  = sqrt(var);
            double c   = g_s.cnt_fix[f];
            nss += (g_s.sum_fp[f] - c * m) / (sd * c);
        }
        sim /= (double)FRAMES;
        nss /= (double)FRAMES;
        double loss = auc + sim + nss;
        out[0] = (float)loss;
        out[1] = (float)auc;
        out[2] = (float)sim;
        out[3] = (float)nss;
    }
}

extern "C" void kernel_launch(void* const* d_in, const int* in_sizes, int n_in,
                              void* d_out, int out_size) {
    const float* pred = (const float*)d_in[0];
    const float* gt   = (const float*)d_in[1];
    const int*   fix  = (const int*)d_in[2];
    float* out = (float*)d_out;

    k_init<<<1, 256>>>();
    k_pre<<<BPF, TPB>>>(pred);
    dim3 gfull(BPF, FRAMES);
    k_main<<<gfull, TPB>>>(pred, gt, fix);
    k_sim<<<gfull, TPB>>>(pred, gt);
    k_auc<<<1, 1024>>>(out);
}

// round 3
// speedup vs baseline: 1.5234x; 1.5234x over previous
#include <cuda_runtime.h>
#include <math.h>

#define FRAMES 32
#define FRAME_ELEMS (720*1280)          // 921600
#define TOTAL_ELEMS (FRAMES*FRAME_ELEMS)
#define NB 8192                         // histogram bins (tie err ~1e-8 in AUC)
#define BPF 225                         // blocks per frame: 225*256*16 = 921600
#define TPB 256
#define NBLK (BPF*FRAMES)

// All fields are valid when zero-initialized (mins stored as max of ~encF).
struct Stats {
    double sum_p[FRAMES];
    double sum_p2[FRAMES];
    double sum_fp[FRAMES];
    double cnt_fix[FRAMES];
    double sum_sim[FRAMES];
    double sum_g;
    unsigned pmin_c, gmin_c;     // global mins: stores max(~encF(x))
    unsigned p0min_c, p0max_e;   // frame-0 pred: min (complement), max (direct)
    float simc[4];               // pmin, gmin, invTp, invTg  (written by last k_main block)
};

__device__ Stats g_s;            // zero at module load; k_auc re-zeros each call
__device__ unsigned g_hf[NB];
__device__ unsigned g_hn[NB];
__device__ unsigned g_ticket;

// ---------- helpers ----------
__device__ __forceinline__ unsigned encF(float x) {
    unsigned u = __float_as_uint(x);
    return (u & 0x80000000u) ? ~u : (u | 0x80000000u);
}
__device__ __forceinline__ float decF(unsigned u) {
    u = (u & 0x80000000u) ? (u & 0x7FFFFFFFu) : ~u;
    return __uint_as_float(u);
}

// 256-thread block reductions (f32)
__device__ __forceinline__ float blkSumF(float v, float* sh) {
    #pragma unroll
    for (int o = 16; o; o >>= 1) v += __shfl_down_sync(0xFFFFFFFFu, v, o);
    if ((threadIdx.x & 31) == 0) sh[threadIdx.x >> 5] = v;
    __syncthreads();
    float r = 0.f;
    if (threadIdx.x < 32) {
        r = (threadIdx.x < 8) ? sh[threadIdx.x] : 0.f;
        #pragma unroll
        for (int o = 4; o; o >>= 1) r += __shfl_down_sync(0xFFFFFFFFu, r, o);
    }
    __syncthreads();
    return r;   // valid on thread 0
}

__device__ __forceinline__ float blkMinF(float v, float* sh) {
    #pragma unroll
    for (int o = 16; o; o >>= 1) v = fminf(v, __shfl_down_sync(0xFFFFFFFFu, v, o));
    if ((threadIdx.x & 31) == 0) sh[threadIdx.x >> 5] = v;
    __syncthreads();
    float r = 3.4e38f;
    if (threadIdx.x < 32) {
        r = (threadIdx.x < 8) ? sh[threadIdx.x] : 3.4e38f;
        #pragma unroll
        for (int o = 4; o; o >>= 1) r = fminf(r, __shfl_down_sync(0xFFFFFFFFu, r, o));
    }
    __syncthreads();
    return r;
}

__device__ __forceinline__ float blkMaxF(float v, float* sh) {
    #pragma unroll
    for (int o = 16; o; o >>= 1) v = fmaxf(v, __shfl_down_sync(0xFFFFFFFFu, v, o));
    if ((threadIdx.x & 31) == 0) sh[threadIdx.x >> 5] = v;
    __syncthreads();
    float r = -3.4e38f;
    if (threadIdx.x < 32) {
        r = (threadIdx.x < 8) ? sh[threadIdx.x] : -3.4e38f;
        #pragma unroll
        for (int o = 4; o; o >>= 1) r = fmaxf(r, __shfl_down_sync(0xFFFFFFFFu, r, o));
    }
    __syncthreads();
    return r;
}

__device__ __forceinline__ unsigned long long blkSumU1024(unsigned long long v,
                                                          unsigned long long* sh) {
    #pragma unroll
    for (int o = 16; o; o >>= 1) v += __shfl_down_sync(0xFFFFFFFFu, v, o);
    if ((threadIdx.x & 31) == 0) sh[threadIdx.x >> 5] = v;
    __syncthreads();
    unsigned long long r = 0;
    if (threadIdx.x < 32) {
        r = sh[threadIdx.x];
        #pragma unroll
        for (int o = 16; o; o >>= 1) r += __shfl_down_sync(0xFFFFFFFFu, r, o);
    }
    __syncthreads();
    return r;
}

// ---------- kernels ----------

// frame-0 pred min/max (for AUC bin scale)
__global__ void __launch_bounds__(TPB) k_pre(const float* __restrict__ pred) {
    __shared__ float shf[8];
    size_t base = (size_t)blockIdx.x * 4096u;
    const float4* p4 = reinterpret_cast<const float4*>(pred + base);
    float4 P[4];
    #pragma unroll
    for (int k = 0; k < 4; k++) P[k] = p4[threadIdx.x + 256 * k];
    float mn = 3.4e38f, mx = -3.4e38f;
    #pragma unroll
    for (int k = 0; k < 4; k++) {
        float4 p = P[k];
        mn = fminf(mn, fminf(fminf(p.x, p.y), fminf(p.z, p.w)));
        mx = fmaxf(mx, fmaxf(fmaxf(p.x, p.y), fmaxf(p.z, p.w)));
    }
    float rmn = blkMinF(mn, shf);
    float rmx = blkMaxF(mx, shf);
    if (threadIdx.x == 0) {
        atomicMax(&g_s.p0min_c, ~encF(rmn));
        atomicMax(&g_s.p0max_e, encF(rmx));
    }
}

// Pass 1: per-frame NSS stats + global mins + frame-0 AUC histogram.
// Last block computes SIM normalization constants.
__global__ void __launch_bounds__(TPB, 3) k_main(const float* __restrict__ pred,
                                                 const float* __restrict__ gt,
                                                 const int* __restrict__ fix) {
    __shared__ float shf[8];
    int f = blockIdx.y;
    size_t base = (size_t)f * FRAME_ELEMS + (size_t)blockIdx.x * 4096u;
    const float4* p4 = reinterpret_cast<const float4*>(pred + base);
    const float4* g4 = reinterpret_cast<const float4*>(gt + base);
    const int4*   x4 = reinterpret_cast<const int4*>(fix + base);

    // batch all loads first (MLP)
    float4 P[4], G[4]; int4 X[4];
    #pragma unroll
    for (int k = 0; k < 4; k++) P[k] = p4[threadIdx.x + 256 * k];
    #pragma unroll
    for (int k = 0; k < 4; k++) G[k] = g4[threadIdx.x + 256 * k];
    #pragma unroll
    for (int k = 0; k < 4; k++) X[k] = x4[threadIdx.x + 256 * k];

    bool doHist = (f == 0);
    float p0min = 0.f, scale = 0.f;
    if (doHist) {
        p0min = decF(~g_s.p0min_c);
        float p0max = decF(g_s.p0max_e);
        scale = (float)NB / (p0max - p0min);
    }

    float sp = 0.f, sp2 = 0.f, sfp = 0.f, sg = 0.f, cf = 0.f;
    float pmn = 3.4e38f, gmn = 3.4e38f;
    #pragma unroll
    for (int k = 0; k < 4; k++) {
        float4 p = P[k]; float4 g = G[k]; int4 x = X[k];
        sp  += (p.x + p.y) + (p.z + p.w);
        sp2 += (p.x*p.x + p.y*p.y) + (p.z*p.z + p.w*p.w);
        sg  += (g.x + g.y) + (g.z + g.w);
        pmn = fminf(pmn, fminf(fminf(p.x, p.y), fminf(p.z, p.w)));
        gmn = fminf(gmn, fminf(fminf(g.x, g.y), fminf(g.z, g.w)));
        if (x.x) { sfp += p.x; cf += 1.f; }
        if (x.y) { sfp += p.y; cf += 1.f; }
        if (x.z) { sfp += p.z; cf += 1.f; }
        if (x.w) { sfp += p.w; cf += 1.f; }
        if (doHist) {
            int b0 = min(NB - 1, (int)((p.x - p0min) * scale));
            int b1 = min(NB - 1, (int)((p.y - p0min) * scale));
            int b2 = min(NB - 1, (int)((p.z - p0min) * scale));
            int b3 = min(NB - 1, (int)((p.w - p0min) * scale));
            atomicAdd(x.x ? &g_hf[b0] : &g_hn[b0], 1u);
            atomicAdd(x.y ? &g_hf[b1] : &g_hn[b1], 1u);
            atomicAdd(x.z ? &g_hf[b2] : &g_hn[b2], 1u);
            atomicAdd(x.w ? &g_hf[b3] : &g_hn[b3], 1u);
        }
    }
    float rs  = blkSumF(sp,  shf);
    float rs2 = blkSumF(sp2, shf);
    float rfp = blkSumF(sfp, shf);
    float rg  = blkSumF(sg,  shf);
    float rcf = blkSumF(cf,  shf);
    float rpmn = blkMinF(pmn, shf);
    float rgmn = blkMinF(gmn, shf);
    if (threadIdx.x == 0) {
        atomicAdd(&g_s.sum_p[f],  (double)rs);
        atomicAdd(&g_s.sum_p2[f], (double)rs2);
        atomicAdd(&g_s.sum_fp[f], (double)rfp);
        atomicAdd(&g_s.cnt_fix[f], (double)rcf);
        atomicAdd(&g_s.sum_g,     (double)rg);
        atomicMax(&g_s.pmin_c, ~encF(rpmn));
        atomicMax(&g_s.gmin_c, ~encF(rgmn));
        __threadfence();
        unsigned t = atomicAdd(&g_ticket, 1u);
        if (t == NBLK - 1u) {
            // last block: finalize SIM constants (read through L2 with .cg)
            float pmin = decF(~g_s.pmin_c);
            float gmin = decF(~g_s.gmin_c);
            double sumP = 0.0;
            #pragma unroll
            for (int ff = 0; ff < FRAMES; ff++) sumP += __ldcg(&g_s.sum_p[ff]);
            double Tp = sumP - (double)TOTAL_ELEMS * (double)pmin;
            double Tg = __ldcg(&g_s.sum_g) - (double)TOTAL_ELEMS * (double)gmin;
            g_s.simc[0] = pmin;
            g_s.simc[1] = gmin;
            g_s.simc[2] = (float)(1.0 / Tp);
            g_s.simc[3] = (float)(1.0 / Tg);
        }
    }
}

// Pass 2: SIM. Reversed iteration order for L2 reuse of k_main's tail.
__global__ void __launch_bounds__(TPB, 4) k_sim(const float* __restrict__ pred,
                                                const float* __restrict__ gt) {
    __shared__ float shf[8];
    int f  = (FRAMES - 1) - blockIdx.y;
    int xb = (BPF - 1) - blockIdx.x;
    size_t base = (size_t)f * FRAME_ELEMS + (size_t)xb * 4096u;
    const float4* p4 = reinterpret_cast<const float4*>(pred + base);
    const float4* g4 = reinterpret_cast<const float4*>(gt + base);

    float pmin = g_s.simc[0], gmin = g_s.simc[1];
    float ip   = g_s.simc[2], ig   = g_s.simc[3];

    float4 P[4], G[4];
    #pragma unroll
    for (int k = 0; k < 4; k++) P[k] = p4[threadIdx.x + 256 * k];
    #pragma unroll
    for (int k = 0; k < 4; k++) G[k] = g4[threadIdx.x + 256 * k];

    float acc = 0.f;
    #pragma unroll
    for (int k = 0; k < 4; k++) {
        float4 p = P[k]; float4 g = G[k];
        if (g.x > gmin) acc += fminf((g.x - gmin) * ig, (p.x - pmin) * ip);
        if (g.y > gmin) acc += fminf((g.y - gmin) * ig, (p.y - pmin) * ip);
        if (g.z > gmin) acc += fminf((g.z - gmin) * ig, (p.z - pmin) * ip);
        if (g.w > gmin) acc += fminf((g.w - gmin) * ig, (p.w - pmin) * ip);
    }
    float r = blkSumF(acc, shf);
    if (threadIdx.x == 0) atomicAdd(&g_s.sum_sim[f], (double)r);
}

// One block: AUC via Mann-Whitney U from the 8192-bin histogram, final output,
// then self-clean all device state for the next graph replay.
__global__ void k_auc(float* __restrict__ out) {
    __shared__ unsigned sc[1024];
    __shared__ unsigned long long shu[32];
    __shared__ int sB;
    int t = threadIdx.x;
    int base = t * 8;
    uint4 a0 = *reinterpret_cast<const uint4*>(&g_hf[base]);
    uint4 a1 = *reinterpret_cast<const uint4*>(&g_hf[base + 4]);
    uint4 b0 = *reinterpret_cast<const uint4*>(&g_hn[base]);
    uint4 b1 = *reinterpret_cast<const uint4*>(&g_hn[base + 4]);
    unsigned hf[8] = {a0.x, a0.y, a0.z, a0.w, a1.x, a1.y, a1.z, a1.w};
    unsigned hn[8] = {b0.x, b0.y, b0.z, b0.w, b1.x, b1.y, b1.z, b1.w};

    unsigned local = 0;
    #pragma unroll
    for (int i = 0; i < 8; i++) local += hf[i];
    if (t == 0) sB = NB;
    sc[t] = local;
    __syncthreads();
    for (int o = 1; o < 1024; o <<= 1) {
        unsigned v = (t >= o) ? sc[t - o] : 0u;
        __syncthreads();
        sc[t] += v;
        __syncthreads();
    }
    unsigned F = sc[t] - local;   // exclusive prefix of fix counts

    int mn = NB;
    #pragma unroll
    for (int i = 0; i < 8; i++) if (hf[i] && base + i < mn) mn = base + i;
    atomicMin(&sB, mn);
    __syncthreads();
    int bstar = sB;

    unsigned long long u1 = 0, u2 = 0, u3 = 0;
    #pragma unroll
    for (int i = 0; i < 8; i++) {
        u1 += (unsigned long long)hn[i] * F;
        u2 += (unsigned long long)hf[i] * hn[i];
        if (base + i > bstar) u3 += hn[i];
        F += hf[i];
    }
    u1 = blkSumU1024(u1, shu);
    u2 = blkSumU1024(u2, shu);
    u3 = blkSumU1024(u3, shu);

    if (t == 0) {
        double Np = (double)FRAME_ELEMS;
        double Nf = g_s.cnt_fix[0];
        double D  = Np - Nf;
        double S  = (double)u1 + 0.5 * (double)u2;
        double b  = (double)u3;
        double auc = ((2.0 * Nf + 1.0) * b + 1.0 - 2.0 * S) / (2.0 * Nf * D)
                   + 1.0 - (b + 1.0) / D;
        double sim = 0.0, nss = 0.0;
        for (int f = 0; f < FRAMES; f++) {
            sim += g_s.sum_sim[f];
            double m   = g_s.sum_p[f] / Np;
            double var = g_s.sum_p2[f] / Np - m * m;
            double sd  = sqrt(var);
            double c   = g_s.cnt_fix[f];
            nss += (g_s.sum_fp[f] - c * m) / (sd * c);
        }
        sim /= (double)FRAMES;
        nss /= (double)FRAMES;
        double loss = auc + sim + nss;
        out[0] = (float)loss;
        out[1] = (float)auc;
        out[2] = (float)sim;
        out[3] = (float)nss;
    }

    // ---- self-clean device state for the next replay ----
    __syncthreads();   // everyone done reading g_hf/g_hn/g_s
    #pragma unroll
    for (int i = 0; i < 2; i++) {
        *reinterpret_cast<uint4*>(&g_hf[base + 4 * i]) = make_uint4(0, 0, 0, 0);
        *reinterpret_cast<uint4*>(&g_hn[base + 4 * i]) = make_uint4(0, 0, 0, 0);
    }
    {
        // zero the whole Stats struct (valid zero-init encodings) + ticket
        unsigned long long* s8 = reinterpret_cast<unsigned long long*>(&g_s);
        int n8 = (int)(sizeof(Stats) / 8);
        if (t <= n8) {
            if (t < n8) s8[t] = 0ull;
            else { /* tail bytes, if any */ }
        }
        if (t == 0) {
            // clear any trailing bytes not covered by 8-byte stores
            char* sc8 = reinterpret_cast<char*>(&g_s);
            for (int i = n8 * 8; i < (int)sizeof(Stats); i++) sc8[i] = 0;
            g_ticket = 0u;
        }
    }
}

extern "C" void kernel_launch(void* const* d_in, const int* in_sizes, int n_in,
                              void* d_out, int out_size) {
    const float* pred = (const float*)d_in[0];
    const float* gt   = (const float*)d_in[1];
    const int*   fix  = (const int*)d_in[2];
    float* out = (float*)d_out;

    k_pre<<<BPF, TPB>>>(pred);
    dim3 gfull(BPF, FRAMES);
    k_main<<<gfull, TPB>>>(pred, gt, fix);
    k_sim<<<gfull, TPB>>>(pred, gt);
    k_auc<<<1, 1024>>>(out);
}

// round 4
// speedup vs baseline: 2.0774x; 1.3637x over previous
#include <cuda_runtime.h>
#include <math.h>

#define FRAMES 32
#define FRAME_ELEMS (720*1280)          // 921600
#define TOTAL_ELEMS (FRAMES*FRAME_ELEMS)
#define NB 8192                         // histogram bins (tie err ~1e-8 in AUC)
#define BPF 225                         // blocks per frame: 225*256*16 = 921600
#define TPB 256
#define NBLK (BPF*FRAMES)

// All fields are valid when zero-initialized (mins stored as max of ~encF).
struct Stats {
    double sum_p[FRAMES];
    double sum_p2[FRAMES];
    double sum_fp[FRAMES];
    double cnt_fix[FRAMES];
    double sum_sim[FRAMES];
    double sum_g;
    unsigned pmin_c, gmin_c;     // global mins: stores max(~encF(x))
    unsigned p0min_c, p0max_e;   // frame-0 pred: min (complement), max (direct)
    float simc[4];               // pmin, gmin, invTp, invTg  (written by last k_main block)
};

__device__ Stats g_s;            // zero at module load; k_auc re-zeros each call
__device__ unsigned g_hf[NB];
__device__ unsigned g_hn[NB];
__device__ unsigned g_ticket;

// ---------- helpers ----------
__device__ __forceinline__ unsigned encF(float x) {
    unsigned u = __float_as_uint(x);
    return (u & 0x80000000u) ? ~u : (u | 0x80000000u);
}
__device__ __forceinline__ float decF(unsigned u) {
    u = (u & 0x80000000u) ? (u & 0x7FFFFFFFu) : ~u;
    return __uint_as_float(u);
}

// 256-thread block reductions (f32)
__device__ __forceinline__ float blkSumF(float v, float* sh) {
    #pragma unroll
    for (int o = 16; o; o >>= 1) v += __shfl_down_sync(0xFFFFFFFFu, v, o);
    if ((threadIdx.x & 31) == 0) sh[threadIdx.x >> 5] = v;
    __syncthreads();
    float r = 0.f;
    if (threadIdx.x < 32) {
        r = (threadIdx.x < 8) ? sh[threadIdx.x] : 0.f;
        #pragma unroll
        for (int o = 4; o; o >>= 1) r += __shfl_down_sync(0xFFFFFFFFu, r, o);
    }
    __syncthreads();
    return r;   // valid on thread 0
}

__device__ __forceinline__ float blkMinF(float v, float* sh) {
    #pragma unroll
    for (int o = 16; o; o >>= 1) v = fminf(v, __shfl_down_sync(0xFFFFFFFFu, v, o));
    if ((threadIdx.x & 31) == 0) sh[threadIdx.x >> 5] = v;
    __syncthreads();
    float r = 3.4e38f;
    if (threadIdx.x < 32) {
        r = (threadIdx.x < 8) ? sh[threadIdx.x] : 3.4e38f;
        #pragma unroll
        for (int o = 4; o; o >>= 1) r = fminf(r, __shfl_down_sync(0xFFFFFFFFu, r, o));
    }
    __syncthreads();
    return r;
}

__device__ __forceinline__ float blkMaxF(float v, float* sh) {
    #pragma unroll
    for (int o = 16; o; o >>= 1) v = fmaxf(v, __shfl_down_sync(0xFFFFFFFFu, v, o));
    if ((threadIdx.x & 31) == 0) sh[threadIdx.x >> 5] = v;
    __syncthreads();
    float r = -3.4e38f;
    if (threadIdx.x < 32) {
        r = (threadIdx.x < 8) ? sh[threadIdx.x] : -3.4e38f;
        #pragma unroll
        for (int o = 4; o; o >>= 1) r = fmaxf(r, __shfl_down_sync(0xFFFFFFFFu, r, o));
    }
    __syncthreads();
    return r;
}

// ---------- kernels ----------

// frame-0 pred min/max (for AUC bin scale)
__global__ void __launch_bounds__(TPB) k_pre(const float* __restrict__ pred) {
    __shared__ float shf[8];
    size_t base = (size_t)blockIdx.x * 4096u;
    const float4* p4 = reinterpret_cast<const float4*>(pred + base);
    float4 P[4];
    #pragma unroll
    for (int k = 0; k < 4; k++) P[k] = p4[threadIdx.x + 256 * k];
    float mn = 3.4e38f, mx = -3.4e38f;
    #pragma unroll
    for (int k = 0; k < 4; k++) {
        float4 p = P[k];
        mn = fminf(mn, fminf(fminf(p.x, p.y), fminf(p.z, p.w)));
        mx = fmaxf(mx, fmaxf(fmaxf(p.x, p.y), fmaxf(p.z, p.w)));
    }
    float rmn = blkMinF(mn, shf);
    float rmx = blkMaxF(mx, shf);
    if (threadIdx.x == 0) {
        atomicMax(&g_s.p0min_c, ~encF(rmn));
        atomicMax(&g_s.p0max_e, encF(rmx));
    }
}

// Pass 1: per-frame NSS stats + global mins + frame-0 AUC histogram.
// Last block computes SIM normalization constants.
__global__ void __launch_bounds__(TPB, 3) k_main(const float* __restrict__ pred,
                                                 const float* __restrict__ gt,
                                                 const int* __restrict__ fix) {
    __shared__ float shf[8];
    int f = blockIdx.y;
    size_t base = (size_t)f * FRAME_ELEMS + (size_t)blockIdx.x * 4096u;
    const float4* p4 = reinterpret_cast<const float4*>(pred + base);
    const float4* g4 = reinterpret_cast<const float4*>(gt + base);
    const int4*   x4 = reinterpret_cast<const int4*>(fix + base);

    // batch all loads first (MLP)
    float4 P[4], G[4]; int4 X[4];
    #pragma unroll
    for (int k = 0; k < 4; k++) P[k] = p4[threadIdx.x + 256 * k];
    #pragma unroll
    for (int k = 0; k < 4; k++) G[k] = g4[threadIdx.x + 256 * k];
    #pragma unroll
    for (int k = 0; k < 4; k++) X[k] = x4[threadIdx.x + 256 * k];

    bool doHist = (f == 0);
    float p0min = 0.f, scale = 0.f;
    if (doHist) {
        p0min = decF(~g_s.p0min_c);
        float p0max = decF(g_s.p0max_e);
        scale = (float)NB / (p0max - p0min);
    }

    float sp = 0.f, sp2 = 0.f, sfp = 0.f, sg = 0.f, cf = 0.f;
    float pmn = 3.4e38f, gmn = 3.4e38f;
    #pragma unroll
    for (int k = 0; k < 4; k++) {
        float4 p = P[k]; float4 g = G[k]; int4 x = X[k];
        sp  += (p.x + p.y) + (p.z + p.w);
        sp2 += (p.x*p.x + p.y*p.y) + (p.z*p.z + p.w*p.w);
        sg  += (g.x + g.y) + (g.z + g.w);
        pmn = fminf(pmn, fminf(fminf(p.x, p.y), fminf(p.z, p.w)));
        gmn = fminf(gmn, fminf(fminf(g.x, g.y), fminf(g.z, g.w)));
        if (x.x) { sfp += p.x; cf += 1.f; }
        if (x.y) { sfp += p.y; cf += 1.f; }
        if (x.z) { sfp += p.z; cf += 1.f; }
        if (x.w) { sfp += p.w; cf += 1.f; }
        if (doHist) {
            int b0 = min(NB - 1, (int)((p.x - p0min) * scale));
            int b1 = min(NB - 1, (int)((p.y - p0min) * scale));
            int b2 = min(NB - 1, (int)((p.z - p0min) * scale));
            int b3 = min(NB - 1, (int)((p.w - p0min) * scale));
            atomicAdd(x.x ? &g_hf[b0] : &g_hn[b0], 1u);
            atomicAdd(x.y ? &g_hf[b1] : &g_hn[b1], 1u);
            atomicAdd(x.z ? &g_hf[b2] : &g_hn[b2], 1u);
            atomicAdd(x.w ? &g_hf[b3] : &g_hn[b3], 1u);
        }
    }
    float rs  = blkSumF(sp,  shf);
    float rs2 = blkSumF(sp2, shf);
    float rfp = blkSumF(sfp, shf);
    float rg  = blkSumF(sg,  shf);
    float rcf = blkSumF(cf,  shf);
    float rpmn = blkMinF(pmn, shf);
    float rgmn = blkMinF(gmn, shf);
    if (threadIdx.x == 0) {
        atomicAdd(&g_s.sum_p[f],  (double)rs);
        atomicAdd(&g_s.sum_p2[f], (double)rs2);
        atomicAdd(&g_s.sum_fp[f], (double)rfp);
        atomicAdd(&g_s.cnt_fix[f], (double)rcf);
        atomicAdd(&g_s.sum_g,     (double)rg);
        atomicMax(&g_s.pmin_c, ~encF(rpmn));
        atomicMax(&g_s.gmin_c, ~encF(rgmn));
        __threadfence();
        unsigned t = atomicAdd(&g_ticket, 1u);
        if (t == NBLK - 1u) {
            float pmin = decF(~g_s.pmin_c);
            float gmin = decF(~g_s.gmin_c);
            double sumP = 0.0;
            #pragma unroll
            for (int ff = 0; ff < FRAMES; ff++) sumP += __ldcg(&g_s.sum_p[ff]);
            double Tp = sumP - (double)TOTAL_ELEMS * (double)pmin;
            double Tg = __ldcg(&g_s.sum_g) - (double)TOTAL_ELEMS * (double)gmin;
            g_s.simc[0] = pmin;
            g_s.simc[1] = gmin;
            g_s.simc[2] = (float)(1.0 / Tp);
            g_s.simc[3] = (float)(1.0 / Tg);
        }
    }
}

// Pass 2: SIM. Reversed iteration order for L2 reuse of k_main's tail.
__global__ void __launch_bounds__(TPB, 4) k_sim(const float* __restrict__ pred,
                                                const float* __restrict__ gt) {
    __shared__ float shf[8];
    int f  = (FRAMES - 1) - blockIdx.y;
    int xb = (BPF - 1) - blockIdx.x;
    size_t base = (size_t)f * FRAME_ELEMS + (size_t)xb * 4096u;
    const float4* p4 = reinterpret_cast<const float4*>(pred + base);
    const float4* g4 = reinterpret_cast<const float4*>(gt + base);

    float pmin = g_s.simc[0], gmin = g_s.simc[1];
    float ip   = g_s.simc[2], ig   = g_s.simc[3];

    float4 P[4], G[4];
    #pragma unroll
    for (int k = 0; k < 4; k++) P[k] = p4[threadIdx.x + 256 * k];
    #pragma unroll
    for (int k = 0; k < 4; k++) G[k] = g4[threadIdx.x + 256 * k];

    float acc = 0.f;
    #pragma unroll
    for (int k = 0; k < 4; k++) {
        float4 p = P[k]; float4 g = G[k];
        if (g.x > gmin) acc += fminf((g.x - gmin) * ig, (p.x - pmin) * ip);
        if (g.y > gmin) acc += fminf((g.y - gmin) * ig, (p.y - pmin) * ip);
        if (g.z > gmin) acc += fminf((g.z - gmin) * ig, (p.z - pmin) * ip);
        if (g.w > gmin) acc += fminf((g.w - gmin) * ig, (p.w - pmin) * ip);
    }
    float r = blkSumF(acc, shf);
    if (threadIdx.x == 0) atomicAdd(&g_s.sum_sim[f], (double)r);
}

// One block, 1024 threads: AUC via Mann-Whitney U + parallel FP64 epilogue,
// then self-clean all device state for the next graph replay.
__global__ void __launch_bounds__(1024) k_auc(float* __restrict__ out) {
    __shared__ unsigned swtot[32];
    __shared__ unsigned long long sU[3];
    __shared__ int sB;
    int t = threadIdx.x;
    int lane = t & 31, wid = t >> 5;

    if (t == 0) { sB = NB; sU[0] = 0ull; sU[1] = 0ull; sU[2] = 0ull; }

    int base = t * 8;
    uint4 a0 = *reinterpret_cast<const uint4*>(&g_hf[base]);
    uint4 a1 = *reinterpret_cast<const uint4*>(&g_hf[base + 4]);
    uint4 b0 = *reinterpret_cast<const uint4*>(&g_hn[base]);
    uint4 b1 = *reinterpret_cast<const uint4*>(&g_hn[base + 4]);
    unsigned hf[8] = {a0.x, a0.y, a0.z, a0.w, a1.x, a1.y, a1.z, a1.w};
    unsigned hn[8] = {b0.x, b0.y, b0.z, b0.w, b1.x, b1.y, b1.z, b1.w};

    unsigned local = 0;
    #pragma unroll
    for (int i = 0; i < 8; i++) local += hf[i];

    // warp-level inclusive scan of per-thread fix counts
    unsigned incl = local;
    #pragma unroll
    for (int o = 1; o < 32; o <<= 1) {
        unsigned v = __shfl_up_sync(0xFFFFFFFFu, incl, o);
        if (lane >= o) incl += v;
    }
    if (lane == 31) swtot[wid] = incl;
    __syncthreads();
    // warp 0 scans the 32 warp totals (exclusive)
    if (wid == 0) {
        unsigned w = swtot[lane];
        unsigned wincl = w;
        #pragma unroll
        for (int o = 1; o < 32; o <<= 1) {
            unsigned v = __shfl_up_sync(0xFFFFFFFFu, wincl, o);
            if (lane >= o) wincl += v;
        }
        swtot[lane] = wincl - w;   // exclusive warp offset
    }
    __syncthreads();
    unsigned F = swtot[wid] + (incl - local);   // exclusive prefix of fix counts

    // bstar = lowest bin containing a fixation
    int mn = NB;
    #pragma unroll
    for (int i = 0; i < 8; i++) if (hf[i] && base + i < mn) mn = base + i;
    #pragma unroll
    for (int o = 16; o; o >>= 1) mn = min(mn, __shfl_down_sync(0xFFFFFFFFu, mn, o));
    if (lane == 0 && mn < NB) atomicMin(&sB, mn);
    __syncthreads();
    int bstar = sB;

    unsigned long long u1 = 0, u2 = 0, u3 = 0;
    #pragma unroll
    for (int i = 0; i < 8; i++) {
        u1 += (unsigned long long)hn[i] * F;       // non-fix vs fix ranked above
        u2 += (unsigned long long)hf[i] * hn[i];   // within-bin ties (expected /2)
        if (base + i > bstar) u3 += hn[i];
        F += hf[i];
    }
    #pragma unroll
    for (int o = 16; o; o >>= 1) {
        u1 += __shfl_down_sync(0xFFFFFFFFu, u1, o);
        u2 += __shfl_down_sync(0xFFFFFFFFu, u2, o);
        u3 += __shfl_down_sync(0xFFFFFFFFu, u3, o);
    }
    if (lane == 0) {
        atomicAdd(&sU[0], u1);
        atomicAdd(&sU[1], u2);
        atomicAdd(&sU[2], u3);
    }
    __syncthreads();

    // ---- parallel epilogue: frame f handled by thread f (warp 0) ----
    if (wid == 0) {
        double Np = (double)FRAME_ELEMS;
        // per-frame NSS + SIM contributions, 32-way parallel
        double m   = g_s.sum_p[lane] / Np;
        double var = g_s.sum_p2[lane] / Np - m * m;
        double sd  = sqrt(var);
        double c   = g_s.cnt_fix[lane];
        double nssf = (g_s.sum_fp[lane] - c * m) / (sd * c);
        double simf = g_s.sum_sim[lane];
        double Nf0 = __shfl_sync(0xFFFFFFFFu, c, 0);   // cnt_fix[0]
        #pragma unroll
        for (int o = 16; o; o >>= 1) {
            nssf += __shfl_down_sync(0xFFFFFFFFu, nssf, o);
            simf += __shfl_down_sync(0xFFFFFFFFu, simf, o);
        }
        if (lane == 0) {
            double Nf = Nf0;
            double D  = Np - Nf;
            double S  = (double)sU[0] + 0.5 * (double)sU[1];
            double b  = (double)sU[2];
            double auc = ((2.0 * Nf + 1.0) * b + 1.0 - 2.0 * S) / (2.0 * Nf * D)
                       + 1.0 - (b + 1.0) / D;
            double sim = simf / (double)FRAMES;
            double nss = nssf / (double)FRAMES;
            double loss = auc + sim + nss;
            out[0] = (float)loss;
            out[1] = (float)auc;
            out[2] = (float)sim;
            out[3] = (float)nss;
        }
    }

    // ---- self-clean device state for the next replay ----
    __syncthreads();   // everyone done reading g_hf/g_hn/g_s
    #pragma unroll
    for (int i = 0; i < 2; i++) {
        *reinterpret_cast<uint4*>(&g_hf[base + 4 * i]) = make_uint4(0, 0, 0, 0);
        *reinterpret_cast<uint4*>(&g_hn[base + 4 * i]) = make_uint4(0, 0, 0, 0);
    }
    {
        unsigned long long* s8 = reinterpret_cast<unsigned long long*>(&g_s);
        int n8 = (int)(sizeof(Stats) / 8);
        if (t < n8) s8[t] = 0ull;
        if (t == 0) {
            char* sc8 = reinterpret_cast<char*>(&g_s);
            for (int i = n8 * 8; i < (int)sizeof(Stats); i++) sc8[i] = 0;
            g_ticket = 0u;
        }
    }
}

extern "C" void kernel_launch(void* const* d_in, const int* in_sizes, int n_in,
                              void* d_out, int out_size) {
    const float* pred = (const float*)d_in[0];
    const float* gt   = (const float*)d_in[1];
    const int*   fix  = (const int*)d_in[2];
    float* out = (float*)d_out;

    k_pre<<<BPF, TPB>>>(pred);
    dim3 gfull(BPF, FRAMES);
    k_main<<<gfull, TPB>>>(pred, gt, fix);
    k_sim<<<gfull, TPB>>>(pred, gt);
    k_auc<<<1, 1024>>>(out);
}